// round 12
// baseline (speedup 1.0000x reference)
#include <cuda_runtime.h>
#include <cstdint>

// Problem constants (fixed by the dataset)
#define BATCH   16
#define C_IN    64
#define HH      32
#define WW      32
#define C_OUT   128
#define RPW     40               // padded row: 4 left + 32 + 4 right
#define CHS     (4*RPW)          // 160 floats: 4 staged rows per channel

// Affine-collapse tables (op h: val = T0 + TA*a + TB*b + TAB*a*b)
__constant__ float CT0[16]  = {0,0,0,0,0,0,0,0, 1, 1, 1, 1, 1, 1, 1, 1};
__constant__ float CTA[16]  = {0,0,1,1,0,0,1,1,-1,-1, 0, 0,-1,-1, 0, 0};
__constant__ float CTB[16]  = {0,0,0,0,1,1,1,1,-1,-1,-1,-1, 0, 0, 0, 0};
__constant__ float CTAB[16] = {0,1,-1,0,-1,0,-2,-1, 1, 2, 0, 1, 0, 1,-1, 0};

// 16B async copy global->shared (LDGSTS.128)
__device__ __forceinline__ void cp16(float* dst_smem, const float* src) {
    uint32_t d = (uint32_t)__cvta_generic_to_shared(dst_smem);
    asm volatile("cp.async.cg.shared.global [%0], [%1], 16;\n" :: "r"(d), "l"(src));
}

// gate(a,b) = c0 + ca*a + cb*b + cab*a*b, factored to 3 FMAs
__device__ __forceinline__ float gate3(const float4 k, float a, float b) {
    return fmaf(fmaf(k.w, b, k.y), a, fmaf(k.z, b, k.x));
}

// ---------------------------------------------------------------------------
// One block per (batch, 2-row tile). The block stages ALL 64 input channels
// for its 4-row window (2 output rows + halo) ONCE, precomputes softmax
// coefficients + leaf offsets for all 128 output channels into smem, then
// each warp computes 16 ocs x 2 rows x 32 cols. Input staging is shared by
// all ocs -> 16x less smem-fill traffic than one-block-per-oc, 4x fewer
// warps, and all per-oc setup amortized.
// ---------------------------------------------------------------------------
__global__ void __launch_bounds__(256, 4)
tree_kernel(const float* __restrict__ x,
            const float* __restrict__ w,
            const int*   __restrict__ leaf_idx,
            float*       __restrict__ out)
{
    __shared__ __align__(16) float  data[C_IN * CHS];   // 40960 B
    __shared__ __align__(16) float4 coef[C_OUT * 4];    //  8192 B
    __shared__ int loff[C_OUT * 8];                     //  4096 B

    const int blk  = blockIdx.x;       // 0..255
    const int b    = blk >> 4;         // batch
    const int tile = blk & 15;         // 2-row tile: output rows 2*tile..2*tile+1
    const int tid  = threadIdx.x;

    // --- stage: 64 ch x 4 rows x 8 chunks = 2048 cp16 (8 per thread) ------
    // local row lr corresponds to global input row 2*tile - 1 + lr.
    {
        float4 z = make_float4(0.f, 0.f, 0.f, 0.f);
        const int grow0 = tile * 2 - 1;
        const float* xb = x + ((size_t)b * C_IN) * (HH * WW);
        #pragma unroll
        for (int i = 0; i < 8; i++) {
            int t    = tid + i * 256;          // 0..2047
            int ch   = t >> 5;
            int lr   = (t >> 3) & 3;
            int c4   = t & 7;
            int grow = grow0 + lr;
            float* dst = data + ch * CHS + lr * RPW + 4 + c4 * 4;
            if ((unsigned)grow < 32u)
                cp16(dst, xb + (ch << 10) + grow * 32 + c4 * 4);
            else
                *(float4*)dst = z;             // halo row outside the image
        }
        asm volatile("cp.async.commit_group;\n");
    }

    // --- side pads: cols 0-3 / 36-39 of 64 ch x 4 rows = 512 float4 -------
    {
        float4 z = make_float4(0.f, 0.f, 0.f, 0.f);
        #pragma unroll
        for (int i = 0; i < 2; i++) {
            int t    = tid + i * 256;          // 0..511
            int ch   = t >> 3;
            int lr   = (t >> 1) & 3;
            int side = t & 1;
            *(float4*)(data + ch * CHS + lr * RPW + side * 36) = z;
        }
    }

    // --- leaf offsets for all 128 ocs: 1024 tasks (4 per thread) ----------
    #pragma unroll
    for (int i = 0; i < 4; i++) {
        int t   = tid + i * 256;               // = oc*8 + leaf
        int idx = __ldg(&leaf_idx[t]);
        int ch  = idx / 9;
        int pos = idx - ch * 9;
        int ki  = pos / 3;
        int kj  = pos - ki * 3;
        loff[t] = ch * CHS + ki * RPW + kj + 3;
    }

    // --- softmax coefficients for all (oc, gate 0..3): 512 tasks ----------
    // op h equals CT0 + CTA*a + CTB*b + CTAB*a*b; same accumulation order
    // as previous rounds (sequential i = 0..15).
    #pragma unroll
    for (int i = 0; i < 2; i++) {
        int t  = tid + i * 256;                // = oc*4 + g
        int oc = t >> 2;
        int g  = t & 3;
        const float* wp = w + (oc * 7 + g) * 16;   // weights [C_out, 7, 16]

        float m = __ldg(wp);
        #pragma unroll
        for (int q = 1; q < 16; q++) m = fmaxf(m, __ldg(wp + q));

        float e[16];
        float s = 0.f;
        #pragma unroll
        for (int q = 0; q < 16; q++) { e[q] = __expf(__ldg(wp + q) - m); s += e[q]; }
        float inv = 1.f / s;

        float c0 = 0.f, ca = 0.f, cb = 0.f, cab = 0.f;
        #pragma unroll
        for (int q = 0; q < 16; q++) {
            c0  += e[q] * CT0[q];
            ca  += e[q] * CTA[q];
            cb  += e[q] * CTB[q];
            cab += e[q] * CTAB[q];
        }
        coef[t] = make_float4(c0 * inv, ca * inv, cb * inv, cab * inv);
    }

    // --- one wait + one barrier ------------------------------------------
    asm volatile("cp.async.wait_group 0;\n");
    __syncthreads();

    // --- compute: warp handles 16 ocs x 2 rows x 32 cols ------------------
    const int lane = tid & 31;
    const int wid  = tid >> 5;
    const float* q = data + lane;              // lane = output column

    float* ob = out + ((size_t)b * C_OUT + wid * 16) * (HH * WW)
                    + (tile * 2) * WW + lane;

    #pragma unroll 4
    for (int j = 0; j < 16; j++) {
        const int oc = wid * 16 + j;

        const float4 k0 = coef[oc * 4 + 0];
        const float4 k1 = coef[oc * 4 + 1];
        const float4 k2 = coef[oc * 4 + 2];
        const float4 k3 = coef[oc * 4 + 3];

        const int4 a0 = ((const int4*)loff)[oc * 2 + 0];
        const int4 a1 = ((const int4*)loff)[oc * 2 + 1];

        #pragma unroll
        for (int r = 0; r < 2; r++) {
            const int d = r * RPW;

            float l0 = q[a0.x + d], l1 = q[a0.y + d];
            float l2 = q[a0.z + d], l3 = q[a0.w + d];
            float l4 = q[a1.x + d], l5 = q[a1.y + d];
            float l6 = q[a1.z + d], l7 = q[a1.w + d];

            // level 0: weight rows 0,1,2,3
            float m0 = gate3(k0, l0, l1);
            float m1 = gate3(k1, l2, l3);
            float m2 = gate3(k2, l4, l5);
            float m3 = gate3(k3, l6, l7);
            // level 1: rows 1,2
            float n0 = gate3(k1, m0, m1);
            float n1 = gate3(k2, m2, m3);
            // level 2: row 3
            float r_ = gate3(k3, n0, n1);

            ob[j * (HH * WW) + r * WW] = r_;
        }
    }
}

extern "C" void kernel_launch(void* const* d_in, const int* in_sizes, int n_in,
                              void* d_out, int out_size)
{
    const float* x   = (const float*)d_in[0];          // [16,64,32,32]
    const float* w   = (const float*)d_in[1];          // [128,7,16]
    const int*   idx = (const int*)d_in[2];            // [128,8]
    float*       out = (float*)d_out;                  // [16,128,32,32]

    tree_kernel<<<BATCH * 16, 256>>>(x, w, idx, out);
}

// round 13
// speedup vs baseline: 1.0345x; 1.0345x over previous
#include <cuda_runtime.h>
#include <cstdint>

// Problem constants (fixed by the dataset)
#define BATCH   16
#define C_IN    64
#define HH      32
#define WW      32
#define C_OUT   128
#define RPW     40               // padded row: 4 left + 32 + 4 right
#define CHS     (4*RPW)          // 160 floats: 4 staged rows per channel
#define OCB     64               // output channels per block (half of C_OUT)

// Affine-collapse tables (op h: val = T0 + TA*a + TB*b + TAB*a*b)
__constant__ float CT0[16]  = {0,0,0,0,0,0,0,0, 1, 1, 1, 1, 1, 1, 1, 1};
__constant__ float CTA[16]  = {0,0,1,1,0,0,1,1,-1,-1, 0, 0,-1,-1, 0, 0};
__constant__ float CTB[16]  = {0,0,0,0,1,1,1,1,-1,-1,-1,-1, 0, 0, 0, 0};
__constant__ float CTAB[16] = {0,1,-1,0,-1,0,-2,-1, 1, 2, 0, 1, 0, 1,-1, 0};

// 16B async copy global->shared (LDGSTS.128)
__device__ __forceinline__ void cp16(float* dst_smem, const float* src) {
    uint32_t d = (uint32_t)__cvta_generic_to_shared(dst_smem);
    asm volatile("cp.async.cg.shared.global [%0], [%1], 16;\n" :: "r"(d), "l"(src));
}

// gate(a,b) = c0 + ca*a + cb*b + cab*a*b, factored to 3 FMAs
__device__ __forceinline__ float gate3(const float4 k, float a, float b) {
    return fmaf(fmaf(k.w, b, k.y), a, fmaf(k.z, b, k.x));
}

// ---------------------------------------------------------------------------
// One block per (batch, 2-row tile, oc-half). The block stages ALL 64 input
// channels for its 4-row window once (shared by its 64 ocs), precomputes
// softmax coefficients + leaf offsets for those 64 ocs, then each warp
// computes 8 ocs x 2 rows x 32 cols. Grid 512 -> ~3.5 blocks/SM, ~28
// warps/SM: enough latency hiding for the LDS-gather + FMA-tree chains,
// while keeping total issued instructions ~30% below the per-oc schemes.
// ---------------------------------------------------------------------------
__global__ void __launch_bounds__(256, 4)
tree_kernel(const float* __restrict__ x,
            const float* __restrict__ w,
            const int*   __restrict__ leaf_idx,
            float*       __restrict__ out)
{
    __shared__ __align__(16) float  data[C_IN * CHS];   // 40960 B
    __shared__ __align__(16) float4 coef[OCB * 4];      //  4096 B
    __shared__ int loff[OCB * 8];                       //  2048 B

    const int blk  = blockIdx.x;       // 0..511
    const int b    = blk >> 5;         // batch
    const int t5   = blk & 31;
    const int tile = t5 >> 1;          // 2-row tile: output rows 2*tile..2*tile+1
    const int oc0  = (t5 & 1) * OCB;   // first output channel of this block
    const int tid  = threadIdx.x;

    // --- stage: 64 ch x 4 rows x 8 chunks = 2048 cp16 (8 per thread) ------
    // local row lr corresponds to global input row 2*tile - 1 + lr.
    {
        float4 z = make_float4(0.f, 0.f, 0.f, 0.f);
        const int grow0 = tile * 2 - 1;
        const float* xb = x + ((size_t)b * C_IN) * (HH * WW);
        #pragma unroll
        for (int i = 0; i < 8; i++) {
            int t    = tid + i * 256;          // 0..2047
            int ch   = t >> 5;
            int lr   = (t >> 3) & 3;
            int c4   = t & 7;
            int grow = grow0 + lr;
            float* dst = data + ch * CHS + lr * RPW + 4 + c4 * 4;
            if ((unsigned)grow < 32u)
                cp16(dst, xb + (ch << 10) + grow * 32 + c4 * 4);
            else
                *(float4*)dst = z;             // halo row outside the image
        }
        asm volatile("cp.async.commit_group;\n");
    }

    // --- side pads: cols 0-3 / 36-39 of 64 ch x 4 rows = 512 float4 -------
    {
        float4 z = make_float4(0.f, 0.f, 0.f, 0.f);
        #pragma unroll
        for (int i = 0; i < 2; i++) {
            int t    = tid + i * 256;          // 0..511
            int ch   = t >> 3;
            int lr   = (t >> 1) & 3;
            int side = t & 1;
            *(float4*)(data + ch * CHS + lr * RPW + side * 36) = z;
        }
    }

    // --- leaf offsets for this block's 64 ocs: 512 tasks (2 per thread) ---
    #pragma unroll
    for (int i = 0; i < 2; i++) {
        int t   = tid + i * 256;               // = ocLocal*8 + leaf
        int idx = __ldg(&leaf_idx[oc0 * 8 + t]);
        int ch  = idx / 9;
        int pos = idx - ch * 9;
        int ki  = pos / 3;
        int kj  = pos - ki * 3;
        loff[t] = ch * CHS + ki * RPW + kj + 3;
    }

    // --- softmax coefficients for (ocLocal, gate 0..3): 256 tasks ---------
    {
        int oc = oc0 + (tid >> 2);             // global oc
        int g  = tid & 3;
        const float* wp = w + (oc * 7 + g) * 16;   // weights [C_out, 7, 16]

        float m = __ldg(wp);
        #pragma unroll
        for (int q = 1; q < 16; q++) m = fmaxf(m, __ldg(wp + q));

        float e[16];
        float s = 0.f;
        #pragma unroll
        for (int q = 0; q < 16; q++) { e[q] = __expf(__ldg(wp + q) - m); s += e[q]; }
        float inv = 1.f / s;

        float c0 = 0.f, ca = 0.f, cb = 0.f, cab = 0.f;
        #pragma unroll
        for (int q = 0; q < 16; q++) {
            c0  += e[q] * CT0[q];
            ca  += e[q] * CTA[q];
            cb  += e[q] * CTB[q];
            cab += e[q] * CTAB[q];
        }
        coef[tid] = make_float4(c0 * inv, ca * inv, cb * inv, cab * inv);
    }

    // --- one wait + one barrier ------------------------------------------
    asm volatile("cp.async.wait_group 0;\n");
    __syncthreads();

    // --- compute: warp handles 8 ocs x 2 rows x 32 cols -------------------
    const int lane = tid & 31;
    const int wid  = tid >> 5;
    const float* q = data + lane;              // lane = output column

    float* ob = out + ((size_t)b * C_OUT + oc0 + wid * 8) * (HH * WW)
                    + (tile * 2) * WW + lane;

    #pragma unroll 4
    for (int j = 0; j < 8; j++) {
        const int ol = wid * 8 + j;            // local oc 0..63

        const float4 k0 = coef[ol * 4 + 0];
        const float4 k1 = coef[ol * 4 + 1];
        const float4 k2 = coef[ol * 4 + 2];
        const float4 k3 = coef[ol * 4 + 3];

        const int4 a0 = ((const int4*)loff)[ol * 2 + 0];
        const int4 a1 = ((const int4*)loff)[ol * 2 + 1];

        #pragma unroll
        for (int r = 0; r < 2; r++) {
            const int d = r * RPW;

            float l0 = q[a0.x + d], l1 = q[a0.y + d];
            float l2 = q[a0.z + d], l3 = q[a0.w + d];
            float l4 = q[a1.x + d], l5 = q[a1.y + d];
            float l6 = q[a1.z + d], l7 = q[a1.w + d];

            // level 0: weight rows 0,1,2,3
            float m0 = gate3(k0, l0, l1);
            float m1 = gate3(k1, l2, l3);
            float m2 = gate3(k2, l4, l5);
            float m3 = gate3(k3, l6, l7);
            // level 1: rows 1,2
            float n0 = gate3(k1, m0, m1);
            float n1 = gate3(k2, m2, m3);
            // level 2: row 3
            float r_ = gate3(k3, n0, n1);

            ob[j * (HH * WW) + r * WW] = r_;
        }
    }
}

extern "C" void kernel_launch(void* const* d_in, const int* in_sizes, int n_in,
                              void* d_out, int out_size)
{
    const float* x   = (const float*)d_in[0];          // [16,64,32,32]
    const float* w   = (const float*)d_in[1];          // [128,7,16]
    const int*   idx = (const int*)d_in[2];            // [128,8]
    float*       out = (float*)d_out;                  // [16,128,32,32]

    tree_kernel<<<BATCH * 16 * 2, 256>>>(x, w, idx, out);
}

// round 14
// speedup vs baseline: 1.5047x; 1.4545x over previous
#include <cuda_runtime.h>
#include <cstdint>

// Problem constants (fixed by the dataset)
#define BATCH   16
#define C_IN    64
#define HH      32
#define WW      32
#define C_OUT   128
#define PW      36          // padded row: 4 left + 32 (leaf col = x+kj+3 <= 35)
#define PLANE   (34*PW)     // 1224 floats (rows 0..33; interior rows 1..32)
#define PLANE4  (PLANE/4)   // 306

// 16B async copy global->shared (LDGSTS.128)
__device__ __forceinline__ void cp16(float* dst_smem, const float* src) {
    uint32_t d = (uint32_t)__cvta_generic_to_shared(dst_smem);
    asm volatile("cp.async.cg.shared.global [%0], [%1], 16;\n" :: "r"(d), "l"(src));
}

// gate(a,b) = c0 + ca*a + cb*b + cab*a*b, factored to 3 FMAs
__device__ __forceinline__ float gate3(const float4 k, float a, float b) {
    return fmaf(fmaf(k.w, b, k.y), a, fmaf(k.z, b, k.x));
}

// ---------------------------------------------------------------------------
// 128-thread block per (batch, oc); grid 2048. 32 regs x 128 thr x 16 blocks
// = exactly one SM's regfile -> 16 blocks/SM cap -> the whole grid is ONE
// wave (~14 blocks, ~55 warps per SM). Small blocks de-phase memory bursts;
// the single barrier covers only 4 warps. Hot loop: 8 LDS + 21 FMA + 1 STG
// per pixel, 8 px/thread, all offsets compile-time.
// ---------------------------------------------------------------------------
__global__ void __launch_bounds__(128, 16)
tree_kernel(const float* __restrict__ x,
            const float* __restrict__ w,
            const int*   __restrict__ leaf_idx,
            float*       __restrict__ out)
{
    __shared__ __align__(16) float  sm[2 * PLANE];   // 9792 B
    __shared__ __align__(16) float  s_coef[16];
    __shared__ int s_off[8];

    const int blk = blockIdx.x;          // 0..2047
    const int oc  = blk & (C_OUT - 1);
    const int b   = blk >> 7;
    const int tid = threadIdx.x;         // 0..127

    // --- channels (broadcast LDG; const-div -> mul-hi) ---------------------
    const int chA = __ldg(&leaf_idx[oc * 8 + 0]) / 9;
    const int chB = __ldg(&leaf_idx[oc * 8 + 4]) / 9;

    // --- leaf offsets: threads 0..7 ----------------------------------------
    if (tid < 8) {
        int idx = __ldg(&leaf_idx[oc * 8 + tid]);
        int ch  = idx / 9;
        int pos = idx - ch * 9;
        int ki  = pos / 3;
        int kj  = pos - ki * 3;
        s_off[tid] = (tid >> 2) * PLANE + ki * PW + kj + 3;
    }

    // --- softmax -> 4 affine coefficients, threads 0..3 (gate = tid) -------
    // op order: 0, ab, a-ab, a, b-ab, b, s-2ab, s-ab, 1-(s-ab), 1-(s-2ab),
    //           1-b, 1-b+ab, 1-a, 1-a+ab, 1-ab, 1
    if (tid < 4) {
        const float T0[16]  = {0,0,0,0,0,0,0,0, 1, 1, 1, 1, 1, 1, 1, 1};
        const float TA[16]  = {0,0,1,1,0,0,1,1,-1,-1, 0, 0,-1,-1, 0, 0};
        const float TB[16]  = {0,0,0,0,1,1,1,1,-1,-1,-1,-1, 0, 0, 0, 0};
        const float TAB[16] = {0,1,-1,0,-1,0,-2,-1, 1, 2, 0, 1, 0, 1,-1, 0};

        const float* wp = w + (oc * 7 + tid) * 16;   // weights [C_out, 7, 16]

        float m = wp[0];
        #pragma unroll
        for (int i = 1; i < 16; i++) m = fmaxf(m, wp[i]);

        float e[16];
        float s = 0.f;
        #pragma unroll
        for (int i = 0; i < 16; i++) { e[i] = __expf(wp[i] - m); s += e[i]; }
        float inv = 1.f / s;

        float c0 = 0.f, ca = 0.f, cb = 0.f, cab = 0.f;
        #pragma unroll
        for (int i = 0; i < 16; i++) {
            c0  += e[i] * T0[i];
            ca  += e[i] * TA[i];
            cb  += e[i] * TB[i];
            cab += e[i] * TAB[i];
        }
        s_coef[tid * 4 + 0] = c0 * inv;
        s_coef[tid * 4 + 1] = ca * inv;
        s_coef[tid * 4 + 2] = cb * inv;
        s_coef[tid * 4 + 3] = cab * inv;
    }

    // --- zero borders: rows 0 & 33 full (9 f4 each) + col-group 0 of rows
    // 1..32 -> 50 float4 per plane, 100 per block (tid < 100, 1 task each) --
    {
        float4 z = make_float4(0.f, 0.f, 0.f, 0.f);
        if (tid < 100) {
            int p = tid >= 50;
            int k = tid - (p ? 50 : 0);
            int f4;
            if (k < 32)      f4 = (k + 1) * (PW / 4);      // rows 1..32, cols 0-3
            else if (k < 41) f4 = (k - 32);                // row 0, groups 0..8
            else             f4 = 33 * (PW / 4) + (k - 41);// row 33, groups 0..8
            ((float4*)sm)[p * PLANE4 + f4] = z;
        }
    }

    // --- stage: 2 planes x 32 rows x 8 chunks = 512 cp16 (4 per thread) ----
    {
        const float* xb = x + ((size_t)b * C_IN) * (HH * WW);
        #pragma unroll
        for (int i = 0; i < 4; i++) {
            int t  = tid + i * 128;      // 0..511
            int p  = t >> 8;
            int j  = t & 255;            // r*8 + c4
            int r  = j >> 3;
            int c4 = j & 7;
            const float* src = xb + ((p ? chB : chA) << 10) + j * 4;
            cp16(sm + p * PLANE + (r + 1) * PW + 4 + c4 * 4, src);
        }
        asm volatile("cp.async.commit_group;\n");
    }

    asm volatile("cp.async.wait_group 0;\n");
    __syncthreads();                     // 4 warps only

    // Coefficients to registers (4x LDS.128)
    const float4* cf = (const float4*)s_coef;
    const float4 k0 = cf[0], k1 = cf[1], k2 = cf[2], k3 = cf[3];

    // Per-thread base pixel: y0 = tid>>5 (0..3), x = tid&31; rows y0+4t
    const int pb0 = (tid >> 5) * PW + (tid & 31);
    const int o0 = s_off[0] + pb0, o1 = s_off[1] + pb0;
    const int o2 = s_off[2] + pb0, o3 = s_off[3] + pb0;
    const int o4 = s_off[4] + pb0, o5 = s_off[5] + pb0;
    const int o6 = s_off[6] + pb0, o7 = s_off[7] + pb0;

    float* ob = out + (size_t)blk * (HH * WW) + tid;

    #pragma unroll
    for (int t = 0; t < 8; t++) {
        const int d = t * 4 * PW;        // +4 rows per step (128 pixels)

        float l0 = sm[o0 + d], l1 = sm[o1 + d];
        float l2 = sm[o2 + d], l3 = sm[o3 + d];
        float l4 = sm[o4 + d], l5 = sm[o5 + d];
        float l6 = sm[o6 + d], l7 = sm[o7 + d];

        // level 0: weight rows 0,1,2,3
        float m0 = gate3(k0, l0, l1);
        float m1 = gate3(k1, l2, l3);
        float m2 = gate3(k2, l4, l5);
        float m3 = gate3(k3, l6, l7);
        // level 1: rows 1,2
        float n0 = gate3(k1, m0, m1);
        float n1 = gate3(k2, m2, m3);
        // level 2: row 3
        float r  = gate3(k3, n0, n1);

        ob[t * 128] = r;
    }
}

extern "C" void kernel_launch(void* const* d_in, const int* in_sizes, int n_in,
                              void* d_out, int out_size)
{
    const float* x   = (const float*)d_in[0];          // [16,64,32,32]
    const float* w   = (const float*)d_in[1];          // [128,7,16]
    const int*   idx = (const int*)d_in[2];            // [128,8]
    float*       out = (float*)d_out;                  // [16,128,32,32]

    tree_kernel<<<BATCH * C_OUT, 128>>>(x, w, idx, out);
}